// round 4
// baseline (speedup 1.0000x reference)
#include <cuda_runtime.h>

#define T_LEN   1000
#define NB      4
#define GRIDB   128
#define THREADS 512

typedef unsigned long long ull;

__device__ float g_xg[512 * T_LEN * 256];   // precomputed input projections (+bias)

__device__ __forceinline__ ull fma2(ull a, ull b, ull c) {
    ull d;
    asm("fma.rn.f32x2 %0, %1, %2, %3;" : "=l"(d) : "l"(a), "l"(b), "l"(c));
    return d;
}
__device__ __forceinline__ ull pack2(float lo, float hi) {
    ull d;
    asm("mov.b64 %0, {%1, %2};" : "=l"(d) : "f"(lo), "f"(hi));
    return d;
}
__device__ __forceinline__ float hadd(ull a) {
    float lo, hi;
    asm("mov.b64 {%0, %1}, %2;" : "=f"(lo), "=f"(hi) : "l"(a));
    return lo + hi;
}
__device__ __forceinline__ float sigf(float x) {
    return __fdividef(1.0f, 1.0f + __expf(-x));
}
__device__ __forceinline__ float tanh_(float x) {
    return 1.0f - __fdividef(2.0f, 1.0f + __expf(2.0f * x));
}

// ---------------- pass 1: xg[b][t][j] = b_ih1[j]+b_hh1[j] + sum_k w_ih1[j][k]*x[b][k][t]
extern "C" __global__ void __launch_bounds__(256)
xg_kernel(const float* __restrict__ x, const float* __restrict__ w_ih1,
          const float* __restrict__ b_ih1, const float* __restrict__ b_hh1)
{
    __shared__ float xt[26 * 100];
    const int tt = blockIdx.x;          // t-tile (0..9), 100 steps each
    const int b  = blockIdx.y;          // batch
    const int j  = threadIdx.x;         // gate row 0..255
    const int t0 = tt * 100;

    const float* xb = x + (size_t)b * 26 * T_LEN;
    for (int idx = j; idx < 26 * 100; idx += 256) {
        const int k = idx / 100, i = idx - k * 100;
        xt[idx] = xb[k * T_LEN + t0 + i];
    }
    float w[26];
    #pragma unroll
    for (int k = 0; k < 26; ++k) w[k] = w_ih1[j * 26 + k];
    const float bias = b_ih1[j] + b_hh1[j];
    __syncthreads();

    float* og = g_xg + ((size_t)b * T_LEN + t0) * 256 + j;
    #pragma unroll 4
    for (int i = 0; i < 100; ++i) {
        float a = bias;
        #pragma unroll
        for (int k = 0; k < 26; ++k) a = fmaf(w[k], xt[k * 100 + i], a);
        og[(size_t)i * 256] = a;
    }
}

// ---------------- pass 2: persistent recurrent kernel ----------------
extern "C" __global__ void __launch_bounds__(THREADS, 1)
lstm_kernel(const float* __restrict__ w_hh1,
            const float* __restrict__ w_ih2, const float* __restrict__ w_hh2,
            const float* __restrict__ b_ih2, const float* __restrict__ b_hh2,
            const float* __restrict__ w_fc1, const float* __restrict__ b_fc1,
            const float* __restrict__ w_fc2, const float* __restrict__ b_fc2,
            float* __restrict__ out)
{
    __shared__ __align__(16) float v1s[NB * 64];   // h1 per batch
    __shared__ __align__(16) float v2s[NB * 96];   // [h1(64) | h2(32)] per batch
    __shared__ float g1s[NB * 256];
    __shared__ float g2s[NB * 128];
    __shared__ float fcs[64];

    const int tid  = threadIdx.x;
    const int b0   = blockIdx.x * NB;
    const bool is1 = tid < 256;
    const int idx2 = tid - 256;                     // LSTM2 local index
    const int row2 = ((idx2 >> 5) << 4) + (idx2 & 15);   // LSTM2 gate row 0..127
    const int k0   = ((idx2 >> 4) & 1) * 48;             // k-split half offset

    // ----- load per-thread weights into 64-bit packed registers -----
    float wt[64];
    float bias2 = 0.f;
    if (is1) {
        #pragma unroll
        for (int k = 0; k < 64; ++k) wt[k] = w_hh1[tid * 64 + k];
    } else {
        #pragma unroll
        for (int k = 0; k < 48; ++k) {
            const int kk = k0 + k;
            wt[k] = (kk < 64) ? w_ih2[row2 * 64 + kk] : w_hh2[row2 * 32 + (kk - 64)];
        }
        #pragma unroll
        for (int k = 48; k < 64; ++k) wt[k] = 0.f;
        bias2 = b_ih2[row2] + b_hh2[row2];
    }
    ull W[32];
    #pragma unroll
    for (int i = 0; i < 32; ++i) W[i] = pack2(wt[2 * i], wt[2 * i + 1]);

    // ----- init state -----
    for (int e = tid; e < NB * 64; e += THREADS) v1s[e] = 0.f;
    for (int e = tid; e < NB * 96; e += THREADS) v2s[e] = 0.f;

    // update roles
    const int u1b = tid >> 6,  u1n = tid & 63;      // LSTM1 state (tid<256)
    const int u2b = idx2 >> 5, u2n = idx2 & 31;     // LSTM2 state (idx2<128)

    // xg prefetch (LSTM1 threads): row = tid, 4 batches
    const float* xgp = g_xg + (size_t)b0 * T_LEN * 256 + tid;
    const size_t BS = (size_t)T_LEN * 256;          // batch stride in xg
    float xr0 = 0.f, xr1 = 0.f, xr2 = 0.f, xr3 = 0.f;
    if (is1) {
        xr0 = xgp[0]; xr1 = xgp[BS]; xr2 = xgp[2 * BS]; xr3 = xgp[3 * BS];
    }

    float c1 = 0.f, c2 = 0.f;
    __syncthreads();

    // iter t: phase A computes gates1(t) [warps 0-7] and gates2(t-1) [warps 8-15]
    //         phase B applies both state updates.
    #pragma unroll 1
    for (int t = 0; t <= T_LEN; ++t) {
        if (is1) {
            // prefetch xg(t+1) a full step ahead
            const int tp = (t + 1 < T_LEN) ? t + 1 : 0;
            const size_t o = (size_t)tp * 256;
            const float n0 = xgp[o], n1 = xgp[BS + o];
            const float n2 = xgp[2 * BS + o], n3 = xgp[3 * BS + o];

            ull a0 = 0, a1 = 0, a2 = 0, a3 = 0;
            #pragma unroll
            for (int q = 0; q < 16; ++q) {
                ulonglong2 v;
                v = *(const ulonglong2*)(v1s + 0 * 64 + q * 4);
                a0 = fma2(W[2 * q], v.x, a0); a0 = fma2(W[2 * q + 1], v.y, a0);
                v = *(const ulonglong2*)(v1s + 1 * 64 + q * 4);
                a1 = fma2(W[2 * q], v.x, a1); a1 = fma2(W[2 * q + 1], v.y, a1);
                v = *(const ulonglong2*)(v1s + 2 * 64 + q * 4);
                a2 = fma2(W[2 * q], v.x, a2); a2 = fma2(W[2 * q + 1], v.y, a2);
                v = *(const ulonglong2*)(v1s + 3 * 64 + q * 4);
                a3 = fma2(W[2 * q], v.x, a3); a3 = fma2(W[2 * q + 1], v.y, a3);
            }
            g1s[0 * 256 + tid] = hadd(a0) + xr0;
            g1s[1 * 256 + tid] = hadd(a1) + xr1;
            g1s[2 * 256 + tid] = hadd(a2) + xr2;
            g1s[3 * 256 + tid] = hadd(a3) + xr3;
            xr0 = n0; xr1 = n1; xr2 = n2; xr3 = n3;
        } else {
            const float* vb = v2s + k0;
            ull a0 = 0, a1 = 0, a2 = 0, a3 = 0;
            #pragma unroll
            for (int q = 0; q < 12; ++q) {
                ulonglong2 v;
                v = *(const ulonglong2*)(vb + 0 * 96 + q * 4);
                a0 = fma2(W[2 * q], v.x, a0); a0 = fma2(W[2 * q + 1], v.y, a0);
                v = *(const ulonglong2*)(vb + 1 * 96 + q * 4);
                a1 = fma2(W[2 * q], v.x, a1); a1 = fma2(W[2 * q + 1], v.y, a1);
                v = *(const ulonglong2*)(vb + 2 * 96 + q * 4);
                a2 = fma2(W[2 * q], v.x, a2); a2 = fma2(W[2 * q + 1], v.y, a2);
                v = *(const ulonglong2*)(vb + 3 * 96 + q * 4);
                a3 = fma2(W[2 * q], v.x, a3); a3 = fma2(W[2 * q + 1], v.y, a3);
            }
            float p0 = hadd(a0), p1 = hadd(a1), p2 = hadd(a2), p3 = hadd(a3);
            p0 += __shfl_xor_sync(0xffffffffu, p0, 16);
            p1 += __shfl_xor_sync(0xffffffffu, p1, 16);
            p2 += __shfl_xor_sync(0xffffffffu, p2, 16);
            p3 += __shfl_xor_sync(0xffffffffu, p3, 16);
            if (k0 == 0) {
                g2s[0 * 128 + row2] = p0 + bias2;
                g2s[1 * 128 + row2] = p1 + bias2;
                g2s[2 * 128 + row2] = p2 + bias2;
                g2s[3 * 128 + row2] = p3 + bias2;
            }
        }
        __syncthreads();                            // gates ready

        if (is1) {
            // LSTM1 state update for (u1b, u1n) -> h1(t)
            const float gi = g1s[u1b * 256 +       u1n];
            const float gf = g1s[u1b * 256 +  64 + u1n];
            const float gg = g1s[u1b * 256 + 128 + u1n];
            const float go = g1s[u1b * 256 + 192 + u1n];
            const float ii = sigf(gi), ff = sigf(gf);
            const float g  = tanh_(gg), oo = sigf(go);
            c1 = ff * c1 + ii * g;
            const float h = oo * tanh_(c1);
            v1s[u1b * 64 + u1n] = h;
            v2s[u1b * 96 + u1n] = h;
        } else if (idx2 < 128 && t > 0) {
            // LSTM2 state update for step t-1 -> h2(t-1)
            const float gi = g2s[u2b * 128 +      u2n];
            const float gf = g2s[u2b * 128 + 32 + u2n];
            const float gg = g2s[u2b * 128 + 64 + u2n];
            const float go = g2s[u2b * 128 + 96 + u2n];
            const float ii = sigf(gi), ff = sigf(gf);
            const float g  = tanh_(gg), oo = sigf(go);
            c2 = ff * c2 + ii * g;
            v2s[u2b * 96 + 64 + u2n] = oo * tanh_(c2);
        }
        __syncthreads();                            // state ready for next iter
    }

    // ----- FC head on final h2 = v2s[b][64..95] -----
    if (tid < 64) {
        const int b = tid >> 4, f = tid & 15;
        float a = __ldg(b_fc1 + f);
        #pragma unroll
        for (int k = 0; k < 32; ++k)
            a += __ldg(w_fc1 + f * 32 + k) * v2s[b * 96 + 64 + k];
        fcs[b * 16 + f] = fmaxf(a, 0.f);
    }
    __syncthreads();
    if (tid < 40) {
        const int b = tid / 10, o = tid - b * 10;
        float a = __ldg(b_fc2 + o);
        #pragma unroll
        for (int k = 0; k < 16; ++k)
            a += __ldg(w_fc2 + o * 16 + k) * fcs[b * 16 + k];
        out[(b0 + b) * 10 + o] = a;
    }
}

extern "C" void kernel_launch(void* const* d_in, const int* in_sizes, int n_in,
                              void* d_out, int out_size) {
    (void)in_sizes; (void)n_in; (void)out_size;
    xg_kernel<<<dim3(10, 512), 256>>>(
        (const float*)d_in[0],   // x
        (const float*)d_in[1],   // w_ih1
        (const float*)d_in[3],   // b_ih1
        (const float*)d_in[4]);  // b_hh1
    lstm_kernel<<<GRIDB, THREADS>>>(
        (const float*)d_in[2],   // w_hh1
        (const float*)d_in[5],   // w_ih2
        (const float*)d_in[6],   // w_hh2
        (const float*)d_in[7],   // b_ih2
        (const float*)d_in[8],   // b_hh2
        (const float*)d_in[9],   // w_fc1
        (const float*)d_in[10],  // b_fc1
        (const float*)d_in[11],  // w_fc2
        (const float*)d_in[12],  // b_fc2
        (float*)d_out);
}

// round 5
// speedup vs baseline: 1.7863x; 1.7863x over previous
#include <cuda_runtime.h>

#define T_LEN   1000
#define NB      4
#define GRIDB   128
#define THREADS 768

typedef unsigned long long ull;

__device__ float g_xg[512 * T_LEN * 256];   // precomputed input projections (+bias)

__device__ __forceinline__ ull fma2(ull a, ull b, ull c) {
    ull d;
    asm("fma.rn.f32x2 %0, %1, %2, %3;" : "=l"(d) : "l"(a), "l"(b), "l"(c));
    return d;
}
__device__ __forceinline__ ull pack2(float lo, float hi) {
    ull d;
    asm("mov.b64 %0, {%1, %2};" : "=l"(d) : "f"(lo), "f"(hi));
    return d;
}
__device__ __forceinline__ float hadd(ull a) {
    float lo, hi;
    asm("mov.b64 {%0, %1}, %2;" : "=f"(lo), "=f"(hi) : "l"(a));
    return lo + hi;
}
__device__ __forceinline__ float sigf(float x) {
    return __fdividef(1.0f, 1.0f + __expf(-x));
}
__device__ __forceinline__ float tanh_(float x) {
    return 1.0f - __fdividef(2.0f, 1.0f + __expf(2.0f * x));
}

// ---------------- pass 1: xg[b][t][j] = b_ih1[j]+b_hh1[j] + sum_k w_ih1[j][k]*x[b][k][t]
extern "C" __global__ void __launch_bounds__(256)
xg_kernel(const float* __restrict__ x, const float* __restrict__ w_ih1,
          const float* __restrict__ b_ih1, const float* __restrict__ b_hh1)
{
    __shared__ float xt[26 * 100];
    const int tt = blockIdx.x;          // t-tile (0..9), 100 steps each
    const int b  = blockIdx.y;          // batch
    const int j  = threadIdx.x;         // gate row 0..255
    const int t0 = tt * 100;

    const float* xb = x + (size_t)b * 26 * T_LEN;
    for (int idx = j; idx < 26 * 100; idx += 256) {
        const int k = idx / 100, i = idx - k * 100;
        xt[idx] = xb[k * T_LEN + t0 + i];
    }
    float w[26];
    #pragma unroll
    for (int k = 0; k < 26; ++k) w[k] = w_ih1[j * 26 + k];
    const float bias = b_ih1[j] + b_hh1[j];
    __syncthreads();

    float* og = g_xg + ((size_t)b * T_LEN + t0) * 256 + j;
    #pragma unroll 4
    for (int i = 0; i < 100; ++i) {
        float a = bias;
        #pragma unroll
        for (int k = 0; k < 26; ++k) a = fmaf(w[k], xt[k * 100 + i], a);
        og[(size_t)i * 256] = a;
    }
}

// ---------------- pass 2: persistent recurrent kernel ----------------
// 768 threads: tid 0..511  = LSTM1, (row 0..255) x (k-half 0/1), 16 ull weights each
//              tid 512..767 = LSTM2, (row 0..127) x (k-half 0/1), 24 ull weights each
// k-halves are lane-paired (xor 16) and combined with one shfl.bfly.
extern "C" __global__ void __launch_bounds__(THREADS, 1)
lstm_kernel(const float* __restrict__ w_hh1,
            const float* __restrict__ w_ih2, const float* __restrict__ w_hh2,
            const float* __restrict__ b_ih2, const float* __restrict__ b_hh2,
            const float* __restrict__ w_fc1, const float* __restrict__ b_fc1,
            const float* __restrict__ w_fc2, const float* __restrict__ b_fc2,
            float* __restrict__ out)
{
    __shared__ __align__(16) float v1s[NB * 64];   // h1 per batch
    __shared__ __align__(16) float v2s[NB * 96];   // [h1(64) | h2(32)] per batch
    __shared__ float g1s[NB * 256];
    __shared__ float g2s[NB * 128];
    __shared__ float fcs[64];

    const int tid   = threadIdx.x;
    const int b0    = blockIdx.x * NB;
    const int wid   = tid >> 5;
    const int lane  = tid & 31;
    const bool is1  = tid < 512;
    const int khalf = lane >> 4;                 // 0 or 1
    const int rloc  = lane & 15;
    const int row   = is1 ? (wid * 16 + rloc)            // 0..255
                          : ((wid - 16) * 16 + rloc);    // 0..127

    // ----- per-thread weights (packed f32x2) -----
    ull W[24];
    float bias2 = 0.f;
    if (is1) {
        const float* wr = w_hh1 + row * 64 + khalf * 32;
        #pragma unroll
        for (int i = 0; i < 16; ++i) W[i] = pack2(wr[2 * i], wr[2 * i + 1]);
        #pragma unroll
        for (int i = 16; i < 24; ++i) W[i] = 0;
    } else {
        float wt[48];
        #pragma unroll
        for (int k = 0; k < 48; ++k) {
            const int kk = khalf * 48 + k;
            wt[k] = (kk < 64) ? w_ih2[row * 64 + kk] : w_hh2[row * 32 + (kk - 64)];
        }
        #pragma unroll
        for (int i = 0; i < 24; ++i) W[i] = pack2(wt[2 * i], wt[2 * i + 1]);
        bias2 = b_ih2[row] + b_hh2[row];
    }

    // ----- init state -----
    for (int e = tid; e < NB * 64; e += THREADS) v1s[e] = 0.f;
    for (int e = tid; e < NB * 96; e += THREADS) v2s[e] = 0.f;

    // state-update roles
    const int u1b = (tid >> 6) & 3, u1n = tid & 63;        // tid<256: LSTM1 state
    const int i2  = tid - 512;
    const int u2b = (i2 >> 5) & 3,  u2n = i2 & 31;         // tid 512..639: LSTM2 state

    // xg prefetch (LSTM1 khalf==0 lanes): row, 4 batches
    const bool xthr = is1 && (khalf == 0);
    const float* xgp = g_xg + (size_t)b0 * T_LEN * 256 + row;
    const size_t BS = (size_t)T_LEN * 256;
    float xr0 = 0.f, xr1 = 0.f, xr2 = 0.f, xr3 = 0.f;
    if (xthr) {
        xr0 = xgp[0]; xr1 = xgp[BS]; xr2 = xgp[2 * BS]; xr3 = xgp[3 * BS];
    }

    float c1 = 0.f, c2 = 0.f;
    __syncthreads();

    // iter t: phase A computes gates1(t) and gates2(t-1); phase B applies updates.
    #pragma unroll 1
    for (int t = 0; t <= T_LEN; ++t) {
        if (is1) {
            // prefetch xg(t+1) a full step ahead
            float n0 = 0.f, n1 = 0.f, n2 = 0.f, n3 = 0.f;
            if (xthr) {
                const int tp = (t + 1 < T_LEN) ? t + 1 : 0;
                const size_t o = (size_t)tp * 256;
                n0 = xgp[o];          n1 = xgp[BS + o];
                n2 = xgp[2 * BS + o]; n3 = xgp[3 * BS + o];
            }
            const float* vb = v1s + khalf * 32;
            ull a0 = 0, a1 = 0, a2 = 0, a3 = 0;
            #pragma unroll
            for (int q = 0; q < 8; ++q) {
                ulonglong2 v;
                v = *(const ulonglong2*)(vb + 0 * 64 + q * 4);
                a0 = fma2(W[2 * q], v.x, a0); a0 = fma2(W[2 * q + 1], v.y, a0);
                v = *(const ulonglong2*)(vb + 1 * 64 + q * 4);
                a1 = fma2(W[2 * q], v.x, a1); a1 = fma2(W[2 * q + 1], v.y, a1);
                v = *(const ulonglong2*)(vb + 2 * 64 + q * 4);
                a2 = fma2(W[2 * q], v.x, a2); a2 = fma2(W[2 * q + 1], v.y, a2);
                v = *(const ulonglong2*)(vb + 3 * 64 + q * 4);
                a3 = fma2(W[2 * q], v.x, a3); a3 = fma2(W[2 * q + 1], v.y, a3);
            }
            float p0 = hadd(a0), p1 = hadd(a1), p2 = hadd(a2), p3 = hadd(a3);
            p0 += __shfl_xor_sync(0xffffffffu, p0, 16);
            p1 += __shfl_xor_sync(0xffffffffu, p1, 16);
            p2 += __shfl_xor_sync(0xffffffffu, p2, 16);
            p3 += __shfl_xor_sync(0xffffffffu, p3, 16);
            if (khalf == 0) {
                g1s[0 * 256 + row] = p0 + xr0;
                g1s[1 * 256 + row] = p1 + xr1;
                g1s[2 * 256 + row] = p2 + xr2;
                g1s[3 * 256 + row] = p3 + xr3;
            }
            xr0 = n0; xr1 = n1; xr2 = n2; xr3 = n3;
        } else {
            const float* vb = v2s + khalf * 48;
            ull a0 = 0, a1 = 0, a2 = 0, a3 = 0;
            #pragma unroll
            for (int q = 0; q < 12; ++q) {
                ulonglong2 v;
                v = *(const ulonglong2*)(vb + 0 * 96 + q * 4);
                a0 = fma2(W[2 * q], v.x, a0); a0 = fma2(W[2 * q + 1], v.y, a0);
                v = *(const ulonglong2*)(vb + 1 * 96 + q * 4);
                a1 = fma2(W[2 * q], v.x, a1); a1 = fma2(W[2 * q + 1], v.y, a1);
                v = *(const ulonglong2*)(vb + 2 * 96 + q * 4);
                a2 = fma2(W[2 * q], v.x, a2); a2 = fma2(W[2 * q + 1], v.y, a2);
                v = *(const ulonglong2*)(vb + 3 * 96 + q * 4);
                a3 = fma2(W[2 * q], v.x, a3); a3 = fma2(W[2 * q + 1], v.y, a3);
            }
            float p0 = hadd(a0), p1 = hadd(a1), p2 = hadd(a2), p3 = hadd(a3);
            p0 += __shfl_xor_sync(0xffffffffu, p0, 16);
            p1 += __shfl_xor_sync(0xffffffffu, p1, 16);
            p2 += __shfl_xor_sync(0xffffffffu, p2, 16);
            p3 += __shfl_xor_sync(0xffffffffu, p3, 16);
            if (khalf == 0) {
                g2s[0 * 128 + row] = p0 + bias2;
                g2s[1 * 128 + row] = p1 + bias2;
                g2s[2 * 128 + row] = p2 + bias2;
                g2s[3 * 128 + row] = p3 + bias2;
            }
        }
        __syncthreads();                            // gates ready

        if (tid < 256) {
            // LSTM1 state update for (u1b, u1n) -> h1(t)
            const float gi = g1s[u1b * 256 +       u1n];
            const float gf = g1s[u1b * 256 +  64 + u1n];
            const float gg = g1s[u1b * 256 + 128 + u1n];
            const float go = g1s[u1b * 256 + 192 + u1n];
            const float ii = sigf(gi), ff = sigf(gf);
            const float g  = tanh_(gg), oo = sigf(go);
            c1 = ff * c1 + ii * g;
            const float h = oo * tanh_(c1);
            v1s[u1b * 64 + u1n] = h;
            v2s[u1b * 96 + u1n] = h;
        } else if (tid >= 512 && i2 < 128 && t > 0) {
            // LSTM2 state update for step t-1 -> h2(t-1)
            const float gi = g2s[u2b * 128 +      u2n];
            const float gf = g2s[u2b * 128 + 32 + u2n];
            const float gg = g2s[u2b * 128 + 64 + u2n];
            const float go = g2s[u2b * 128 + 96 + u2n];
            const float ii = sigf(gi), ff = sigf(gf);
            const float g  = tanh_(gg), oo = sigf(go);
            c2 = ff * c2 + ii * g;
            v2s[u2b * 96 + 64 + u2n] = oo * tanh_(c2);
        }
        __syncthreads();                            // state ready for next iter
    }

    // ----- FC head on final h2 = v2s[b][64..95] -----
    if (tid < 64) {
        const int b = tid >> 4, f = tid & 15;
        float a = __ldg(b_fc1 + f);
        #pragma unroll
        for (int k = 0; k < 32; ++k)
            a += __ldg(w_fc1 + f * 32 + k) * v2s[b * 96 + 64 + k];
        fcs[b * 16 + f] = fmaxf(a, 0.f);
    }
    __syncthreads();
    if (tid < 40) {
        const int b = tid / 10, o = tid - b * 10;
        float a = __ldg(b_fc2 + o);
        #pragma unroll
        for (int k = 0; k < 16; ++k)
            a += __ldg(w_fc2 + o * 16 + k) * fcs[b * 16 + k];
        out[(b0 + b) * 10 + o] = a;
    }
}

extern "C" void kernel_launch(void* const* d_in, const int* in_sizes, int n_in,
                              void* d_out, int out_size) {
    (void)in_sizes; (void)n_in; (void)out_size;
    xg_kernel<<<dim3(10, 512), 256>>>(
        (const float*)d_in[0],   // x
        (const float*)d_in[1],   // w_ih1
        (const float*)d_in[3],   // b_ih1
        (const float*)d_in[4]);  // b_hh1
    lstm_kernel<<<GRIDB, THREADS>>>(
        (const float*)d_in[2],   // w_hh1
        (const float*)d_in[5],   // w_ih2
        (const float*)d_in[6],   // w_hh2
        (const float*)d_in[7],   // b_ih2
        (const float*)d_in[8],   // b_hh2
        (const float*)d_in[9],   // w_fc1
        (const float*)d_in[10],  // b_fc1
        (const float*)d_in[11],  // w_fc2
        (const float*)d_in[12],  // b_fc2
        (float*)d_out);
}